// round 1
// baseline (speedup 1.0000x reference)
#include <cuda_runtime.h>
#include <cuda_bf16.h>
#include <cstdint>

// Depth-to-space, SCALE=2.
// in : [B=16, H=128, W=128, C=256] fp32
// out: [B, 2H=256, 2W=256, C/4=64] fp32
// out[b, 2h+j, 2w+k, c] = in[b, h, w, 4c + 2k + j]
//
// Each thread: one float4 load (input channels 4c..4c+3 of one pixel),
// four coalesced scalar stores (the 4 (j,k) output positions, same c).
//   v.x -> (j=0,k=0), v.y -> (j=1,k=0), v.z -> (j=0,k=1), v.w -> (j=1,k=1)

__global__ void __launch_bounds__(256, 8)
d2s_kernel(const float4* __restrict__ in4, float* __restrict__ out)
{
    // 16 * 128 * 128 pixels * 64 float4-groups = 16,777,216 threads
    unsigned idx = blockIdx.x * 256u + threadIdx.x;

    unsigned c     = idx & 63u;          // output channel 0..63
    unsigned pixel = idx >> 6;           // b*H*W + h*W + w
    unsigned w     = pixel & 127u;
    unsigned h     = (pixel >> 7) & 127u;
    unsigned b     = pixel >> 14;

    float4 v = in4[idx];                 // in + pixel*256 + 4c floats

    // output row r0 = b*256 + 2h, col c0 = 2w; offset = (r*256 + col)*64 + c
    unsigned r0  = (b << 8) + (h << 1);
    unsigned o00 = (r0 << 14) + (w << 7) + c;   // (r0*256 + 2w)*64 + c
    unsigned o10 = o00 + (1u << 14);            // next output row (j=1)
    unsigned o01 = o00 + 64u;                   // next output col (k=1)
    unsigned o11 = o10 + 64u;

    out[o00] = v.x;   // j=0,k=0  (ch 4c+0)
    out[o10] = v.y;   // j=1,k=0  (ch 4c+1)
    out[o01] = v.z;   // j=0,k=1  (ch 4c+2)
    out[o11] = v.w;   // j=1,k=1  (ch 4c+3)
}

extern "C" void kernel_launch(void* const* d_in, const int* in_sizes, int n_in,
                              void* d_out, int out_size)
{
    const float4* in4 = (const float4*)d_in[0];
    float* out = (float*)d_out;

    // total threads = in_sizes[0] / 4 = 16,777,216
    unsigned n_threads = (unsigned)(in_sizes[0] / 4);
    unsigned n_blocks  = (n_threads + 255u) / 256u;

    d2s_kernel<<<n_blocks, 256>>>(in4, out);
}

// round 2
// speedup vs baseline: 1.0047x; 1.0047x over previous
#include <cuda_runtime.h>
#include <cuda_bf16.h>
#include <cstdint>

// Depth-to-space, SCALE=2.
// in : [B=16, H=128, W=128, C=256] fp32
// out: [B, 2H=256, 2W=256, C/4=64] fp32
// out[b, 2h+j, 2w+k, c] = in[b, h, w, 4c + 2k + j]
//
// Each thread handles 16 consecutive input floats (channels 16g..16g+15 of
// one pixel) via 4 front-batched LDG.128, and writes 4 STG.128:
// output channels 4g..4g+3 at each of the four (j,k) positions.
// Component (2k+j) of loaded float4 m is input channel 16g+4m+2k+j,
// which is output channel 4g+m at position (j,k).  All stores per warp are
// contiguous 256 B runs -> fully coalesced.

__global__ void __launch_bounds__(256, 8)
d2s_kernel(const float4* __restrict__ in4, float4* __restrict__ out4)
{
    // 16*128*128 pixels * 16 groups = 4,194,304 threads
    unsigned idx = blockIdx.x * 256u + threadIdx.x;

    unsigned g     = idx & 15u;          // channel group: out ch 4g..4g+3
    unsigned pixel = idx >> 4;           // b*H*W + h*W + w
    unsigned w     = pixel & 127u;
    unsigned h     = (pixel >> 7) & 127u;
    unsigned b     = pixel >> 14;

    // Front-batched loads: 64 B contiguous per thread, MLP_p1 = 4
    unsigned base4 = idx << 2;
    float4 v0 = in4[base4 + 0];
    float4 v1 = in4[base4 + 1];
    float4 v2 = in4[base4 + 2];
    float4 v3 = in4[base4 + 3];

    // Transpose the 4x4: s_jk = component (2k+j) of {v0,v1,v2,v3}
    float4 s00 = make_float4(v0.x, v1.x, v2.x, v3.x);  // j=0,k=0
    float4 s10 = make_float4(v0.y, v1.y, v2.y, v3.y);  // j=1,k=0
    float4 s01 = make_float4(v0.z, v1.z, v2.z, v3.z);  // j=0,k=1
    float4 s11 = make_float4(v0.w, v1.w, v2.w, v3.w);  // j=1,k=1

    // Output offsets in float4 units:
    // o(j,k) = ((r0+j)*256 + 2w+k)*64/4 + g = ((r0+j)<<12) + ((2w+k)<<4) + g
    unsigned r0  = (b << 8) + (h << 1);            // output row for j=0
    unsigned o00 = (r0 << 12) + (w << 5) + g;
    unsigned o10 = o00 + (1u << 12);               // +1 output row
    unsigned o01 = o00 + 16u;                      // +1 output col
    unsigned o11 = o10 + 16u;

    out4[o00] = s00;
    out4[o10] = s10;
    out4[o01] = s01;
    out4[o11] = s11;
}

extern "C" void kernel_launch(void* const* d_in, const int* in_sizes, int n_in,
                              void* d_out, int out_size)
{
    const float4* in4 = (const float4*)d_in[0];
    float4* out4 = (float4*)d_out;

    // total threads = in_sizes[0] / 16 = 4,194,304
    unsigned n_threads = (unsigned)(in_sizes[0] / 16);
    unsigned n_blocks  = (n_threads + 255u) / 256u;

    d2s_kernel<<<n_blocks, 256>>>(in4, out4);
}

// round 3
// speedup vs baseline: 1.0055x; 1.0008x over previous
#include <cuda_runtime.h>
#include <cuda_bf16.h>
#include <cstdint>

// Depth-to-space, SCALE=2.
// in : [B=16, H=128, W=128, C=256] fp32
// out: [B, 2H=256, 2W=256, C/4=64] fp32
// out[b, 2h+j, 2w+k, c] = in[b, h, w, 4c + 2k + j]
//
// Each thread handles TWO super-indices (split-half apart): per super-index,
// 16 consecutive input floats (4x LDG.128 front-batched -> MLP_p1=8 total),
// then a 4x4 component transpose and 4x STG.128 to the four (j,k) positions.
// All loads/stores are 128B-coalesced per warp. Streaming hints (.cs) keep
// the 512MB stream from thrashing L2.

__device__ __forceinline__ void d2s_offsets(unsigned idx,
                                            unsigned& o00, unsigned& o10,
                                            unsigned& o01, unsigned& o11)
{
    unsigned g     = idx & 15u;          // channel group: out ch 4g..4g+3
    unsigned pixel = idx >> 4;           // b*H*W + h*W + w
    unsigned w     = pixel & 127u;
    unsigned h     = (pixel >> 7) & 127u;
    unsigned b     = pixel >> 14;
    unsigned r0    = (b << 8) + (h << 1);          // output row for j=0
    o00 = (r0 << 12) + (w << 5) + g;               // float4 units
    o10 = o00 + (1u << 12);                        // +1 output row
    o01 = o00 + 16u;                               // +1 output col
    o11 = o10 + 16u;
}

__global__ void __launch_bounds__(256, 4)
d2s_kernel(const float4* __restrict__ in4, float4* __restrict__ out4)
{
    // 4,194,304 super-indices total; each thread takes idx and idx + 2^21
    const unsigned HALF = 1u << 21;
    unsigned idx  = blockIdx.x * 256u + threadIdx.x;
    unsigned idx2 = idx + HALF;

    unsigned ba = idx  << 2;
    unsigned bb = idx2 << 2;

    // 8 front-batched streaming loads (64B x2 contiguous regions per thread)
    float4 a0 = __ldcs(in4 + ba + 0);
    float4 a1 = __ldcs(in4 + ba + 1);
    float4 a2 = __ldcs(in4 + ba + 2);
    float4 a3 = __ldcs(in4 + ba + 3);
    float4 b0 = __ldcs(in4 + bb + 0);
    float4 b1 = __ldcs(in4 + bb + 1);
    float4 b2 = __ldcs(in4 + bb + 2);
    float4 b3 = __ldcs(in4 + bb + 3);

    unsigned o00, o10, o01, o11;
    d2s_offsets(idx, o00, o10, o01, o11);

    // s_jk = component (2k+j) of the 4 loaded vectors
    __stcs(out4 + o00, make_float4(a0.x, a1.x, a2.x, a3.x));  // j=0,k=0
    __stcs(out4 + o10, make_float4(a0.y, a1.y, a2.y, a3.y));  // j=1,k=0
    __stcs(out4 + o01, make_float4(a0.z, a1.z, a2.z, a3.z));  // j=0,k=1
    __stcs(out4 + o11, make_float4(a0.w, a1.w, a2.w, a3.w));  // j=1,k=1

    unsigned p00, p10, p01, p11;
    d2s_offsets(idx2, p00, p10, p01, p11);

    __stcs(out4 + p00, make_float4(b0.x, b1.x, b2.x, b3.x));
    __stcs(out4 + p10, make_float4(b0.y, b1.y, b2.y, b3.y));
    __stcs(out4 + p01, make_float4(b0.z, b1.z, b2.z, b3.z));
    __stcs(out4 + p11, make_float4(b0.w, b1.w, b2.w, b3.w));
}

extern "C" void kernel_launch(void* const* d_in, const int* in_sizes, int n_in,
                              void* d_out, int out_size)
{
    const float4* in4 = (const float4*)d_in[0];
    float4* out4 = (float4*)d_out;

    // threads = (in_sizes[0] / 16) / 2 = 2,097,152
    unsigned n_threads = (unsigned)(in_sizes[0] / 32);
    unsigned n_blocks  = (n_threads + 255u) / 256u;   // 8192

    d2s_kernel<<<n_blocks, 256>>>(in4, out4);
}